// round 15
// baseline (speedup 1.0000x reference)
#include <cuda_runtime.h>

// HiPoNet collapse: P = 0.5*(Wm/colsum) + 0.5*I is column-stochastic, so
// 1^T P^t = 1^T and mean_n(P^t X) = mean_n(X) exactly. Output:
//   out[b, w*160 + k*32 + d] = mean_n(pc[b,n,d]) * alphas[w,d], k=0..4.
//
// R15: R14 (row partition + zero-wait RED + memset node) with
//  - red.global.add.v4.f32 combine: 160 vector REDs/block (4x fewer L2
//    atomic ops than 640 scalar), 16B-aligned addresses
//  - RC=16 (grid=64, one wave): 128 full 128B rows per block ->
//    128 L1tex line-wavefronts/SM (4th halving of the fill term)
//  - per-block skewed RED windows (10 vec-slots) to keep the 16
//    contributors of a batch on disjoint output stripes.

#define NPTS   2048
#define DIM    32
#define NW     4
#define NCOLL  5
#define FOUT   (NW * NCOLL * DIM)        // 640 per batch
#define VOUT   (FOUT / 4)                // 160 float4 outputs per batch
#define RC     16                        // row chunks per batch
#define BLK    512
#define ROWS   (NPTS / RC)               // 128 rows per block
#define QPR    (DIM / 4)                 // 8 float4 per row
#define NWARP  (BLK / 32)                // 16 warps
#define LPT    2                         // loads per thread

__device__ __forceinline__ float4 f4add(float4 a, float4 b) {
    return make_float4(a.x + b.x, a.y + b.y, a.z + b.z, a.w + b.w);
}

__global__ __launch_bounds__(BLK, 1)
void hiponet_kernel(const float* __restrict__ pc,
                    const float* __restrict__ alphas,
                    float* __restrict__ out)
{
    const int b  = blockIdx.x >> 4;      // batch 0..3
    const int rc = blockIdx.x & 15;      // row chunk 0..15
    const int t  = threadIdx.x;          // 0..511
    const int q  = t & (QPR - 1);        // float4 slot in row, 0..7
    const int rg = t >> 3;               // row group, 0..63

    __shared__ float sm[NWARP][DIM];     // per-warp partials
    __shared__ float mean_s[DIM];
    __shared__ float al[NW * DIM];

    if (t < NW * DIM) al[t] = alphas[t]; // overlaps DRAM latency

    // ---- 128 full rows, 2 independent LDG.128 per thread ----
    const float4* __restrict__ base =
        (const float4*)(pc + ((size_t)b * NPTS + rc * ROWS) * DIM);

    float4 v0 = base[(size_t)rg * QPR + q];
    float4 v1 = base[(size_t)(rg + 64) * QPR + q];
    float4 s  = f4add(v0, v1);

    // warp reduce over the 4 row-groups in this warp (lane bits 3,4)
    #pragma unroll
    for (int m = 8; m <= 16; m <<= 1) {
        s.x += __shfl_xor_sync(0xffffffffu, s.x, m);
        s.y += __shfl_xor_sync(0xffffffffu, s.y, m);
        s.z += __shfl_xor_sync(0xffffffffu, s.z, m);
        s.w += __shfl_xor_sync(0xffffffffu, s.w, m);
    }
    if ((t & 31) < QPR)                  // lanes 0..7: warp's 8-row sums
        *(float4*)&sm[t >> 5][q * 4] = s;
    __syncthreads();

    if (t < DIM) {                       // d = t: sum 16 warp partials
        float acc = 0.f;
        #pragma unroll
        for (int i = 0; i < 16; ++i) acc += sm[i][t];
        mean_s[t] = acc * (1.0f / (float)NPTS);
    }
    __syncthreads();

    // ---- zero-wait combine: 160 red.global.add.v4.f32, skewed ----
    float* __restrict__ ob = out + b * FOUT;
    if (t < VOUT) {
        int j = t + rc * (VOUT / RC);    // 10-slot disjoint windows
        if (j >= VOUT) j -= VOUT;
        const int i4 = j * 4;            // float index, multiple of 4
        const int w  = i4 / (NCOLL * DIM);
        const int d  = i4 & 31;          // multiple of 4, no wrap in a row
        const float4 m4 = *(const float4*)&mean_s[d];
        const float4 a4 = *(const float4*)&al[w * DIM + d];
        asm volatile(
            "red.global.add.v4.f32 [%0], {%1, %2, %3, %4};"
            :: "l"(ob + i4),
               "f"(m4.x * a4.x), "f"(m4.y * a4.y),
               "f"(m4.z * a4.z), "f"(m4.w * a4.w)
            : "memory");
    }
}

extern "C" void kernel_launch(void* const* d_in, const int* in_sizes, int n_in,
                              void* d_out, int out_size)
{
    const float* pc     = (const float*)d_in[0];  // [4, 2048, 32] fp32
    // d_in[1] = sigma: output is invariant to the diffusion operator
    const float* alphas = (const float*)d_in[2];  // [4, 32] fp32
    float* out = (float*)d_out;                   // [4, 640] fp32

    // out poisoned to 0xAA; RED combining requires zero-init each replay.
    cudaMemsetAsync(d_out, 0, (size_t)out_size * sizeof(float), 0);
    hiponet_kernel<<<4 * RC, BLK>>>(pc, alphas, out);
}

// round 16
// speedup vs baseline: 1.0047x; 1.0047x over previous
#include <cuda_runtime.h>

// HiPoNet collapse: P = 0.5*(Wm/colsum) + 0.5*I is column-stochastic, so
// 1^T P^t = 1^T and mean_n(P^t X) = mean_n(X) exactly. Output:
//   out[b, w*160 + k*32 + d] = mean_n(pc[b,n,d]) * alphas[w,d], k=0..4.
//
// R16: exactly R14's proven config (grid=32 = batch x 8 row-chunks,
// BLK=512, 4 independent LDG.128/thread, 256 full 128B rows/block,
// kernel 4.38us) with ONE change: the combine is 160
// red.global.add.v4.f32 per block (skewed 20-slot windows) instead of
// 640 scalar REDs -> 4x fewer L2 atomic ops on the fire-and-forget
// drain. Graph = memset(out) node + kernel node.

#define NPTS   2048
#define DIM    32
#define NW     4
#define NCOLL  5
#define FOUT   (NW * NCOLL * DIM)        // 640 per batch
#define VOUT   (FOUT / 4)                // 160 float4 outputs per batch
#define RC     8                         // row chunks per batch
#define BLK    512
#define ROWS   (NPTS / RC)               // 256 rows per block
#define QPR    (DIM / 4)                 // 8 float4 per row
#define NWARP  (BLK / 32)                // 16 warps
#define LPT    4                         // loads per thread

__device__ __forceinline__ float4 f4add(float4 a, float4 b) {
    return make_float4(a.x + b.x, a.y + b.y, a.z + b.z, a.w + b.w);
}

__global__ __launch_bounds__(BLK, 1)
void hiponet_kernel(const float* __restrict__ pc,
                    const float* __restrict__ alphas,
                    float* __restrict__ out)
{
    const int b  = blockIdx.x >> 3;      // batch 0..3
    const int rc = blockIdx.x & 7;       // row chunk 0..7
    const int t  = threadIdx.x;          // 0..511
    const int q  = t & (QPR - 1);        // float4 slot in row, 0..7
    const int rg = t >> 3;               // row group, 0..63

    __shared__ float sm[NWARP][DIM];     // per-warp partials
    __shared__ float mean_s[DIM];
    __shared__ float al[NW * DIM];

    if (t < NW * DIM) al[t] = alphas[t]; // overlaps DRAM latency

    // ---- 256 full rows, 4 independent LDG.128 per thread ----
    const float4* __restrict__ base =
        (const float4*)(pc + ((size_t)b * NPTS + rc * ROWS) * DIM);

    float4 v[LPT];
    #pragma unroll
    for (int k = 0; k < LPT; ++k)
        v[k] = base[(size_t)(rg + (k << 6)) * QPR + q];
    float4 s = f4add(f4add(v[0], v[1]), f4add(v[2], v[3]));

    // warp reduce over the 4 row-groups in this warp (lane bits 3,4)
    #pragma unroll
    for (int m = 8; m <= 16; m <<= 1) {
        s.x += __shfl_xor_sync(0xffffffffu, s.x, m);
        s.y += __shfl_xor_sync(0xffffffffu, s.y, m);
        s.z += __shfl_xor_sync(0xffffffffu, s.z, m);
        s.w += __shfl_xor_sync(0xffffffffu, s.w, m);
    }
    if ((t & 31) < QPR)                  // lanes 0..7: warp's 16-row sums
        *(float4*)&sm[t >> 5][q * 4] = s;
    __syncthreads();

    if (t < DIM) {                       // d = t: sum 16 warp partials
        float acc = 0.f;
        #pragma unroll
        for (int i = 0; i < 16; ++i) acc += sm[i][t];
        mean_s[t] = acc * (1.0f / (float)NPTS);
    }
    __syncthreads();

    // ---- zero-wait combine: 160 red.global.add.v4.f32, skewed ----
    float* __restrict__ ob = out + b * FOUT;
    if (t < VOUT) {
        int j = t + rc * (VOUT / RC);    // 20-slot disjoint windows
        if (j >= VOUT) j -= VOUT;
        const int i4 = j * 4;            // float index, multiple of 4
        const int w  = i4 / (NCOLL * DIM);
        const int d  = i4 & 31;          // multiple of 4; aligned row chunk
        const float4 m4 = *(const float4*)&mean_s[d];
        const float4 a4 = *(const float4*)&al[w * DIM + d];
        asm volatile(
            "red.global.add.v4.f32 [%0], {%1, %2, %3, %4};"
            :: "l"(ob + i4),
               "f"(m4.x * a4.x), "f"(m4.y * a4.y),
               "f"(m4.z * a4.z), "f"(m4.w * a4.w)
            : "memory");
    }
}

extern "C" void kernel_launch(void* const* d_in, const int* in_sizes, int n_in,
                              void* d_out, int out_size)
{
    const float* pc     = (const float*)d_in[0];  // [4, 2048, 32] fp32
    // d_in[1] = sigma: output is invariant to the diffusion operator
    const float* alphas = (const float*)d_in[2];  // [4, 32] fp32
    float* out = (float*)d_out;                   // [4, 640] fp32

    // out poisoned to 0xAA; RED combining requires zero-init each replay.
    cudaMemsetAsync(d_out, 0, (size_t)out_size * sizeof(float), 0);
    hiponet_kernel<<<4 * RC, BLK>>>(pc, alphas, out);
}

// round 17
// speedup vs baseline: 1.0385x; 1.0337x over previous
#include <cuda_runtime.h>

// HiPoNet collapse: P = 0.5*(Wm/colsum) + 0.5*I is column-stochastic, so
// 1^T P^t = 1^T and mean_n(P^t X) = mean_n(X) exactly. Output:
//   out[b, w*160 + k*32 + d] = mean_n(pc[b,n,d]) * alphas[w,d], k=0..4.
//
// R17: R14's RED kernel (grid=32 = batch x 8 row chunks, BLK=512,
// 4 independent LDG.128/thread, skewed scalar REDs) with the memset
// GRAPH NODE folded into the kernel: block 0 zeroes out (640 STG.128,
// overlapped with the other blocks' ~3us load phase), fences, sets
// g_flag; every block polls g_flag once right before its REDs (long
// set by then -> one L2 read). Reset for graph replay: each block
// bumps g_cnt after issuing REDs; the 32nd clears flag+cnt. Graph is
// back to ONE node (the ~0.9us memset-node replay tax is gone).

#define NPTS   2048
#define DIM    32
#define NW     4
#define NCOLL  5
#define FOUT   (NW * NCOLL * DIM)        // 640 per batch
#define RC     8                         // row chunks per batch
#define GRID   (4 * RC)                  // 32 blocks
#define BLK    512
#define ROWS   (NPTS / RC)               // 256 rows per block
#define QPR    (DIM / 4)                 // 8 float4 per row
#define NWARP  (BLK / 32)                // 16 warps
#define LPT    4                         // loads per thread

__device__ unsigned int g_flag;          // zero-init; 1 = out zeroed
__device__ unsigned int g_cnt;           // zero-init; RED-issue arrivals

__device__ __forceinline__ float4 f4add(float4 a, float4 b) {
    return make_float4(a.x + b.x, a.y + b.y, a.z + b.z, a.w + b.w);
}

__global__ __launch_bounds__(BLK, 1)
void hiponet_kernel(const float* __restrict__ pc,
                    const float* __restrict__ alphas,
                    float* __restrict__ out)
{
    const int b  = blockIdx.x >> 3;      // batch 0..3
    const int rc = blockIdx.x & 7;       // row chunk 0..7
    const int t  = threadIdx.x;          // 0..511
    const int q  = t & (QPR - 1);        // float4 slot in row, 0..7
    const int rg = t >> 3;               // row group, 0..63

    __shared__ float sm[NWARP][DIM];     // per-warp partials
    __shared__ float mean_s[DIM];
    __shared__ float al[NW * DIM];

    // ---- block 0: zero the output, release the flag ----
    if (blockIdx.x == 0) {
        float4* __restrict__ oz = (float4*)out;
        oz[t] = make_float4(0.f, 0.f, 0.f, 0.f);          // 0..511
        if (t < 4 * FOUT / 4 - BLK)                        // 512..639
            oz[t + BLK] = make_float4(0.f, 0.f, 0.f, 0.f);
        __syncthreads();
        if (t == 0) {
            __threadfence();
            g_flag = 1u;
        }
    }

    if (t < NW * DIM) al[t] = alphas[t]; // overlaps DRAM latency

    // ---- 256 full rows, 4 independent LDG.128 per thread ----
    const float4* __restrict__ base =
        (const float4*)(pc + ((size_t)b * NPTS + rc * ROWS) * DIM);

    float4 v[LPT];
    #pragma unroll
    for (int k = 0; k < LPT; ++k)
        v[k] = base[(size_t)(rg + (k << 6)) * QPR + q];
    float4 s = f4add(f4add(v[0], v[1]), f4add(v[2], v[3]));

    // warp reduce over the 4 row-groups in this warp (lane bits 3,4)
    #pragma unroll
    for (int m = 8; m <= 16; m <<= 1) {
        s.x += __shfl_xor_sync(0xffffffffu, s.x, m);
        s.y += __shfl_xor_sync(0xffffffffu, s.y, m);
        s.z += __shfl_xor_sync(0xffffffffu, s.z, m);
        s.w += __shfl_xor_sync(0xffffffffu, s.w, m);
    }
    if ((t & 31) < QPR)                  // lanes 0..7: warp's 16-row sums
        *(float4*)&sm[t >> 5][q * 4] = s;
    __syncthreads();

    if (t < DIM) {                       // d = t: sum 16 warp partials
        float acc = 0.f;
        #pragma unroll
        for (int i = 0; i < 16; ++i) acc += sm[i][t];
        mean_s[t] = acc * (1.0f / (float)NPTS);
    }

    // ---- wait for the zeroed output (normally already set) ----
    if (t == 0) {
        volatile unsigned int* f = &g_flag;
        while (*f == 0u) { }
    }
    __syncthreads();                     // flag observed + mean_s ready

    // ---- zero-wait combine: 640 scalar REDs, block-skewed order ----
    float* __restrict__ ob = out + b * FOUT;
    const int skew = rc * (FOUT / RC);   // 80-element disjoint windows
    #pragma unroll
    for (int j = t; j < FOUT; j += BLK) {
        int i = j + skew;
        if (i >= FOUT) i -= FOUT;
        const int w = i / (NCOLL * DIM);
        const int d = i & 31;
        atomicAdd(&ob[i], mean_s[d] * al[w * DIM + d]);
    }

    // ---- replay reset: 32nd arrival clears flag + counter ----
    if (t == 0) {
        unsigned int v2 = atomicAdd(&g_cnt, 1u);
        if (v2 == GRID - 1) {
            g_cnt  = 0u;
            g_flag = 0u;
        }
    }
}

extern "C" void kernel_launch(void* const* d_in, const int* in_sizes, int n_in,
                              void* d_out, int out_size)
{
    const float* pc     = (const float*)d_in[0];  // [4, 2048, 32] fp32
    // d_in[1] = sigma: output is invariant to the diffusion operator
    const float* alphas = (const float*)d_in[2];  // [4, 32] fp32
    float* out = (float*)d_out;                   // [4, 640] fp32

    hiponet_kernel<<<GRID, BLK>>>(pc, alphas, out);
}